// round 11
// baseline (speedup 1.0000x reference)
#include <cuda_runtime.h>
#include <math.h>
#include <stdint.h>

// Problem constants
#define BB   32
#define HH   16
#define SS   577
#define SM1  576      // S-1 patch tokens
#define DD   1024
#define TOPK 289

#define HGRP 4                     // head-groups in reduce kernel
#define HPER (HH / HGRP)           // heads per group = 4

typedef unsigned long long u64;

// Device-global scratch (no allocations allowed)
__device__ int   g_topk_idx[BB * TOPK];
__device__ float g_pre_part [BB * HGRP * SS];
__device__ float g_post_part[BB * HGRP * SS];

__device__ __forceinline__ u64 u64min(u64 a, u64 b) { return a < b ? a : b; }
__device__ __forceinline__ u64 u64max(u64 a, u64 b) { return a > b ? a : b; }

// L2 evict-last policy load: pin this line in L2 across graph replays.
// Scalar ld with inline evict_last is illegal on sm_103a; the cache_hint
// form with a createpolicy register is the supported scalar path.
__device__ __forceinline__ u64 make_evict_last_policy() {
    u64 pol;
    asm("createpolicy.fractional.L2::evict_last.b64 %0, 1.0;" : "=l"(pol));
    return pol;
}
__device__ __forceinline__ float ldg_el(const float* p, u64 pol) {
    float v;
    asm("ld.global.nc.L2::cache_hint.f32 %0, [%1], %2;"
        : "=f"(v) : "l"(p), "l"(pol));
    return v;
}

// ---------------------------------------------------------------------------
// Kernel A: partial head-sums. grid (BB, HGRP) = 128 blocks, 512 threads.
// The touched attention lines (~39MB: pre column stride-2308B + post row) are
// identical every replay and DRAM-hostile (32B useful / 128B line), so pin
// them in L2 with an evict_last policy. The streaming gather (evict_first)
// won't displace them. Steady-state: reduce runs from L2.
// ---------------------------------------------------------------------------
__global__ void __launch_bounds__(512) reduce_kernel(
    const float* __restrict__ pre, const float* __restrict__ post)
{
    const int b   = blockIdx.x;
    const int hg  = blockIdx.y;
    const int tid = threadIdx.x;
    const int h0  = hg * HPER;

    const u64 pol = make_evict_last_policy();

    const size_t baseb = (size_t)b * HH * SS * SS;
    const int    pout  = (b * HGRP + hg) * SS;

    for (int q = tid; q < SS; q += 512) {
        float accp = 0.f, accr = 0.f;
        #pragma unroll
        for (int h = 0; h < HPER; h++) {
            accp += ldg_el(&pre [baseb + ((size_t)(h0 + h) * SS + q) * SS], pol); // col 0
            accr += ldg_el(&post[baseb +  (size_t)(h0 + h) * SS * SS + q],  pol); // row 0
        }
        g_pre_part [pout + q] = accp;
        g_post_part[pout + q] = accr;
    }
}

// ---------------------------------------------------------------------------
// Kernel B: per-batch softmax + exact top-k (lax.top_k ordering).
// 32 blocks x 512 threads. Reads L2-hot partials. Register bitonic sort:
// thread t owns positions 2t, 2t+1; j<=32 on shuffles, j>=64 via shared.
// ---------------------------------------------------------------------------
__global__ void __launch_bounds__(512) maws_topk_kernel(void)
{
    const int b   = blockIdx.x;
    const int tid = threadIdx.x;

    __shared__ float m[SS];        // mean pre column (then exp)
    __shared__ float p[SS];        // mean post row
    __shared__ float red[16];
    __shared__ u64   sh[1024];

    const int pbase = b * HGRP * SS;

    for (int q = tid; q < SS; q += 512) {
        float am = 0.f, ap = 0.f;
        #pragma unroll
        for (int g = 0; g < HGRP; g++) {
            am += g_pre_part [pbase + g * SS + q];
            ap += g_post_part[pbase + g * SS + q];
        }
        m[q] = am * (1.0f / HH);
        p[q] = ap * (1.0f / HH);
    }
    __syncthreads();

    // ---- softmax over m[0..S-1] ----
    float lmax = -INFINITY;
    for (int q = tid; q < SS; q += 512) lmax = fmaxf(lmax, m[q]);
    #pragma unroll
    for (int o = 16; o > 0; o >>= 1)
        lmax = fmaxf(lmax, __shfl_down_sync(0xffffffffu, lmax, o));
    if ((tid & 31) == 0) red[tid >> 5] = lmax;
    __syncthreads();
    if (tid < 32) {
        float v = (tid < 16) ? red[tid] : -INFINITY;
        #pragma unroll
        for (int o = 8; o > 0; o >>= 1)
            v = fmaxf(v, __shfl_down_sync(0xffffffffu, v, o));
        if (tid == 0) red[0] = v;
    }
    __syncthreads();
    const float mx = red[0];
    __syncthreads();

    float lsum = 0.f;
    for (int q = tid; q < SS; q += 512) {
        float e = expf(m[q] - mx);
        m[q] = e;
        lsum += e;
    }
    #pragma unroll
    for (int o = 16; o > 0; o >>= 1)
        lsum += __shfl_down_sync(0xffffffffu, lsum, o);
    if ((tid & 31) == 0) red[tid >> 5] = lsum;
    __syncthreads();
    if (tid < 32) {
        float v = (tid < 16) ? red[tid] : 0.f;
        #pragma unroll
        for (int o = 8; o > 0; o >>= 1)
            v += __shfl_down_sync(0xffffffffu, v, o);
        if (tid == 0) red[0] = v;
    }
    __syncthreads();
    const float inv_sum = 1.0f / red[0];
    __syncthreads();

    // ---- build sort keys in registers: (value desc, index asc) ----
    const int ia = 2 * tid;
    const int ib = 2 * tid + 1;
    u64 a, bk;
    {
        u64 k2[2];
        #pragma unroll
        for (int c = 0; c < 2; c++) {
            int i = ia + c;
            if (i < SM1) {
                float w = m[i + 1] * inv_sum * p[i + 1];   // maws[i]
                unsigned int fb = __float_as_uint(w);
                unsigned int u  = (fb & 0x80000000u) ? ~fb : (fb | 0x80000000u);
                k2[c] = ((u64)(~u) << 32) | (unsigned int)i;
            } else {
                k2[c] = 0xFFFFFFFFFFFFFFFFull;  // padding sorts last
            }
        }
        a = k2[0]; bk = k2[1];
    }

    // ---- bitonic sort ascending, 1024 keys, 2 keys/thread ----
    #pragma unroll
    for (unsigned int k = 2; k <= 1024; k <<= 1) {
        for (unsigned int j = k >> 1; j >= 64; j >>= 1) {   // far: shared
            sh[ia] = a; sh[ib] = bk;
            __syncthreads();
            u64 pa = sh[ia ^ j];
            u64 pb = sh[ib ^ j];
            bool keep_min = (((ia & k) == 0) == ((ia & j) == 0));
            a  = keep_min ? u64min(a,  pa) : u64max(a,  pa);
            bk = keep_min ? u64min(bk, pb) : u64max(bk, pb);
            __syncthreads();
        }
        unsigned int jstart = (k >> 1) < 32 ? (k >> 1) : 32;
        for (unsigned int j = jstart; j >= 2; j >>= 1) {    // near: shuffles
            u64 pa = __shfl_xor_sync(0xffffffffu, a,  j >> 1);
            u64 pb = __shfl_xor_sync(0xffffffffu, bk, j >> 1);
            bool keep_min = (((ia & k) == 0) == ((ia & j) == 0));
            a  = keep_min ? u64min(a,  pa) : u64max(a,  pa);
            bk = keep_min ? u64min(bk, pb) : u64max(bk, pb);
        }
        {                                                    // j == 1
            bool up = ((ia & k) == 0);
            u64 mn = u64min(a, bk), mxk = u64max(a, bk);
            a  = up ? mn  : mxk;
            bk = up ? mxk : mn;
        }
    }

    if (ia < TOPK) g_topk_idx[b * TOPK + ia] = (int)(a  & 0xFFFFFFFFu);
    if (ib < TOPK) g_topk_idx[b * TOPK + ib] = (int)(bk & 0xFFFFFFFFu);
}

// ---------------------------------------------------------------------------
// Kernel C: row gather. 16 rows/block, 578 blocks (one full wave at 4/SM),
// 512 threads x 8 independent float4 streaming (evict-first) copies, so the
// 114MB of streaming traffic does not displace the pinned attention lines.
// out[b, k, :] = feats[b, idx[b,k], :]
// ---------------------------------------------------------------------------
#define ROWS_PER_BLK 16
#define CHUNKS 8                      // 512 * 8 = 16 rows * 256 float4
__global__ void __launch_bounds__(512) gather_kernel(
    const float4* __restrict__ feats4, float4* __restrict__ out4)
{
    const int R = blockIdx.x * ROWS_PER_BLK;
    const int t = threadIdx.x;

    __shared__ size_t s_src[ROWS_PER_BLK];   // source row base (float4 units)
    if (t < ROWS_PER_BLK) {
        int row = R + t;
        int b   = row / TOPK;
        int src = g_topk_idx[row];
        s_src[t] = ((size_t)b * SS + (size_t)src) * 256;
    }
    __syncthreads();

    float4 v[CHUNKS];
    int    rows[CHUNKS], cols[CHUNKS];
    #pragma unroll
    for (int u = 0; u < CHUNKS; u++) {
        int idx = u * 512 + t;                // 0..4095
        rows[u] = idx >> 8;                   // local row 0..15
        cols[u] = idx & 255;
        v[u] = __ldcs(&feats4[s_src[rows[u]] + cols[u]]);
    }
    #pragma unroll
    for (int u = 0; u < CHUNKS; u++)
        __stcs(&out4[((size_t)R + rows[u]) * 256 + cols[u]], v[u]);
}

// ---------------------------------------------------------------------------
// Inputs (metadata order): d_in[0]=feats [B,S,D] f32,
//                          d_in[1]=pre_sm_attn [B,H,S,S] f32,
//                          d_in[2]=post_sm_attn [B,H,S,S] f32
// Output: top_feats [B,TOPK,D] f32
// ---------------------------------------------------------------------------
extern "C" void kernel_launch(void* const* d_in, const int* in_sizes, int n_in,
                              void* d_out, int out_size)
{
    const float* feats = (const float*)d_in[0];
    const float* pre   = (const float*)d_in[1];
    const float* post  = (const float*)d_in[2];
    float* out = (float*)d_out;

    reduce_kernel<<<dim3(BB, HGRP), 512>>>(pre, post);
    maws_topk_kernel<<<BB, 512>>>();
    gather_kernel<<<(BB * TOPK) / ROWS_PER_BLK, 512>>>(
        (const float4*)feats, (float4*)out);
}